// round 2
// baseline (speedup 1.0000x reference)
#include <cuda_runtime.h>
#include <math.h>

// Problem constants: B=4, S=4096, D=1024
#define BATCH 4
#define SEQ   4096
#define DIM   1024

// Static device scratch (allocation-free rule: __device__ globals are allowed)
__device__ float g_Q[(size_t)BATCH * SEQ * DIM];          //  64 MB
__device__ float g_K[(size_t)BATCH * SEQ * DIM];          //  64 MB
__device__ float g_V[(size_t)BATCH * SEQ * DIM];          //  64 MB
__device__ float g_Sc[(size_t)BATCH * SEQ * SEQ];         // 268 MB

// ---------------------------------------------------------------------------
// Tiled SGEMM: C[M,N] = alpha * A * op(B)
//   A: [M,K] row-major
//   BT=true : B is [N,K] row-major, compute A @ B^T   (x@W^T, Q@K^T)
//   BT=false: B is [K,N] row-major, compute A @ B     (P@V)
// Batched via blockIdx.z with element strides sA/sB/sC.
// BM=BN=128, BK=16, 256 threads, 8x8 accumulators per thread.
// All dims are multiples of tile sizes for this problem -> no bounds checks.
// ---------------------------------------------------------------------------
template <bool BT>
__global__ void __launch_bounds__(256, 2)
gemm128(const float* __restrict__ A, const float* __restrict__ B,
        float* __restrict__ C, int M, int N, int K, float alpha,
        long long sA, long long sB, long long sC)
{
    constexpr int BM = 128, BN = 128, BK = 16;
    __shared__ float As[BK][BM];
    __shared__ float Bs[BK][BN];

    A += (size_t)blockIdx.z * sA;
    B += (size_t)blockIdx.z * sB;
    C += (size_t)blockIdx.z * sC;

    const int m0 = blockIdx.y * BM;
    const int n0 = blockIdx.x * BN;
    const int tid = threadIdx.x;
    const int tx = tid & 15;         // 0..15 -> 8 cols each
    const int ty = tid >> 4;         // 0..15 -> 8 rows each

    float acc[8][8] = {};

    for (int k0 = 0; k0 < K; k0 += BK) {
        // --- load A tile [BM x BK] into As[k][m] (transposed) ---
        #pragma unroll
        for (int i = 0; i < 2; i++) {
            int idx = tid + i * 256;          // 512 float4 loads total
            int row = idx >> 2;               // 0..127
            int c4  = idx & 3;                // 0..3 (4 float4 per row)
            float4 t = *(const float4*)&A[(size_t)(m0 + row) * K + k0 + c4 * 4];
            As[c4 * 4 + 0][row] = t.x;
            As[c4 * 4 + 1][row] = t.y;
            As[c4 * 4 + 2][row] = t.z;
            As[c4 * 4 + 3][row] = t.w;
        }
        // --- load B tile ---
        if (BT) {
            #pragma unroll
            for (int i = 0; i < 2; i++) {
                int idx = tid + i * 256;
                int row = idx >> 2;           // n index 0..127
                int c4  = idx & 3;
                float4 t = *(const float4*)&B[(size_t)(n0 + row) * K + k0 + c4 * 4];
                Bs[c4 * 4 + 0][row] = t.x;
                Bs[c4 * 4 + 1][row] = t.y;
                Bs[c4 * 4 + 2][row] = t.z;
                Bs[c4 * 4 + 3][row] = t.w;
            }
        } else {
            #pragma unroll
            for (int i = 0; i < 2; i++) {
                int idx = tid + i * 256;
                int row = idx >> 5;           // k index 0..15 (32 float4 per row)
                int c4  = idx & 31;
                *(float4*)&Bs[row][c4 * 4] =
                    *(const float4*)&B[(size_t)(k0 + row) * N + n0 + c4 * 4];
            }
        }
        __syncthreads();

        // --- compute ---
        #pragma unroll
        for (int k = 0; k < BK; k++) {
            float a[8], b[8];
            *(float4*)&a[0] = *(const float4*)&As[k][ty * 8 + 0];
            *(float4*)&a[4] = *(const float4*)&As[k][ty * 8 + 4];
            *(float4*)&b[0] = *(const float4*)&Bs[k][tx * 8 + 0];
            *(float4*)&b[4] = *(const float4*)&Bs[k][tx * 8 + 4];
            #pragma unroll
            for (int i = 0; i < 8; i++)
                #pragma unroll
                for (int j = 0; j < 8; j++)
                    acc[i][j] += a[i] * b[j];
        }
        __syncthreads();
    }

    // --- epilogue ---
    #pragma unroll
    for (int i = 0; i < 8; i++) {
        float4 o0, o1;
        o0.x = acc[i][0] * alpha; o0.y = acc[i][1] * alpha;
        o0.z = acc[i][2] * alpha; o0.w = acc[i][3] * alpha;
        o1.x = acc[i][4] * alpha; o1.y = acc[i][5] * alpha;
        o1.z = acc[i][6] * alpha; o1.w = acc[i][7] * alpha;
        size_t base = (size_t)(m0 + ty * 8 + i) * N + n0 + tx * 8;
        *(float4*)&C[base + 0] = o0;
        *(float4*)&C[base + 4] = o1;
    }
}

// ---------------------------------------------------------------------------
// Row softmax over SEQ=4096 columns, one block (256 threads) per row.
// Values held in registers: single global read + single global write.
// ---------------------------------------------------------------------------
__device__ __forceinline__ float warpMax(float v) {
    #pragma unroll
    for (int o = 16; o; o >>= 1) v = fmaxf(v, __shfl_xor_sync(0xffffffffu, v, o));
    return v;
}
__device__ __forceinline__ float warpSum(float v) {
    #pragma unroll
    for (int o = 16; o; o >>= 1) v += __shfl_xor_sync(0xffffffffu, v, o);
    return v;
}

__global__ void __launch_bounds__(256)
softmax_rows(float* __restrict__ P)
{
    __shared__ float shm[8];
    __shared__ float shs[8];
    const size_t row = blockIdx.x;
    float4* r4 = (float4*)(P + row * (size_t)SEQ);
    const int tid  = threadIdx.x;
    const int lane = tid & 31;
    const int wid  = tid >> 5;

    float4 v[4];
    float m = -3.4e38f;
    #pragma unroll
    for (int i = 0; i < 4; i++) {
        v[i] = r4[tid + i * 256];
        m = fmaxf(m, fmaxf(fmaxf(v[i].x, v[i].y), fmaxf(v[i].z, v[i].w)));
    }
    m = warpMax(m);
    if (lane == 0) shm[wid] = m;
    __syncthreads();
    float bm = shm[0];
    #pragma unroll
    for (int i = 1; i < 8; i++) bm = fmaxf(bm, shm[i]);

    float s = 0.f;
    #pragma unroll
    for (int i = 0; i < 4; i++) {
        v[i].x = __expf(v[i].x - bm);
        v[i].y = __expf(v[i].y - bm);
        v[i].z = __expf(v[i].z - bm);
        v[i].w = __expf(v[i].w - bm);
        s += v[i].x + v[i].y + v[i].z + v[i].w;
    }
    s = warpSum(s);
    if (lane == 0) shs[wid] = s;
    __syncthreads();
    float bs = 0.f;
    #pragma unroll
    for (int i = 0; i < 8; i++) bs += shs[i];
    float inv = 1.0f / bs;

    #pragma unroll
    for (int i = 0; i < 4; i++) {
        v[i].x *= inv; v[i].y *= inv; v[i].z *= inv; v[i].w *= inv;
        r4[tid + i * 256] = v[i];
    }
}

// ---------------------------------------------------------------------------
// Launch
// ---------------------------------------------------------------------------
extern "C" void kernel_launch(void* const* d_in, const int* in_sizes, int n_in,
                              void* d_out, int out_size)
{
    const float* x  = (const float*)d_in[0];
    const float* Wq = (const float*)d_in[1];
    const float* Wk = (const float*)d_in[2];
    const float* Wv = (const float*)d_in[3];
    float* out = (float*)d_out;

    float *Q, *K, *V, *Sc;
    cudaGetSymbolAddress((void**)&Q,  g_Q);
    cudaGetSymbolAddress((void**)&K,  g_K);
    cudaGetSymbolAddress((void**)&V,  g_V);
    cudaGetSymbolAddress((void**)&Sc, g_Sc);

    const int M  = BATCH * SEQ;     // 16384
    const float scale = 1.0f / 32.0f;   // D^-0.5 = 1/sqrt(1024)

    dim3 blk(256);

    // 1) QKV projections: [16384,1024] = x @ W^T  (NT)
    {
        dim3 grid(DIM / 128, M / 128, 1);
        gemm128<true><<<grid, blk>>>(x, Wq, Q, M, DIM, DIM, 1.0f, 0, 0, 0);
        gemm128<true><<<grid, blk>>>(x, Wk, K, M, DIM, DIM, 1.0f, 0, 0, 0);
        gemm128<true><<<grid, blk>>>(x, Wv, V, M, DIM, DIM, 1.0f, 0, 0, 0);
    }

    // 2) Scores: Sc[b] = scale * Q[b] @ K[b]^T   (NT, batched over z)
    {
        dim3 grid(SEQ / 128, SEQ / 128, BATCH);
        gemm128<true><<<grid, blk>>>(Q, K, Sc, SEQ, SEQ, DIM, scale,
                                     (long long)SEQ * DIM,
                                     (long long)SEQ * DIM,
                                     (long long)SEQ * SEQ);
    }

    // 3) Row softmax over all B*S rows
    softmax_rows<<<BATCH * SEQ, blk>>>(Sc);

    // 4) Out: out[b] = Sc[b] @ V[b]   (NN, batched over z)
    {
        dim3 grid(DIM / 128, SEQ / 128, BATCH);
        gemm128<false><<<grid, blk>>>(Sc, V, out, SEQ, DIM, SEQ, 1.0f,
                                      (long long)SEQ * SEQ,
                                      (long long)SEQ * DIM,
                                      (long long)SEQ * DIM);
    }
}

// round 8
// speedup vs baseline: 2.9411x; 2.9411x over previous
#include <cuda_runtime.h>
#include <cuda_bf16.h>
#include <math.h>
#include <stdint.h>

// Problem: B=4, S=4096, D=1024  (single-head attention, fp32 I/O)
#define BATCH 4
#define SEQ   4096
#define DIM   1024
#define MTOT  (BATCH*SEQ)   // 16384

// ---------------------------------------------------------------------------
// Static device scratch (~600 MB total)
// ---------------------------------------------------------------------------
__device__ __align__(256) __nv_bfloat16 g_xh[(size_t)MTOT * DIM];
__device__ __align__(256) __nv_bfloat16 g_xl[(size_t)MTOT * DIM];
__device__ __align__(256) __nv_bfloat16 g_Wh[3][(size_t)DIM * DIM];
__device__ __align__(256) __nv_bfloat16 g_Wl[3][(size_t)DIM * DIM];
__device__ __align__(256) __nv_bfloat16 g_Qh[(size_t)MTOT * DIM];
__device__ __align__(256) __nv_bfloat16 g_Ql[(size_t)MTOT * DIM];
__device__ __align__(256) __nv_bfloat16 g_Kh[(size_t)MTOT * DIM];
__device__ __align__(256) __nv_bfloat16 g_Kl[(size_t)MTOT * DIM];
__device__ __align__(256) float         g_V [(size_t)MTOT * DIM];
__device__ __align__(256) __nv_bfloat16 g_Vth[(size_t)BATCH * DIM * SEQ];
__device__ __align__(256) __nv_bfloat16 g_Vtl[(size_t)BATCH * DIM * SEQ];
// Union buffer: fp32 scores, then overwritten in-place by split-bf16 P.
// Row r (of BATCH*SEQ): fp32 Sc row = 16KB; after softmax the same 16KB holds
// Ph row (8KB, bf16[4096]) followed by Pl row (8KB).
__device__ __align__(256) float         g_SP[(size_t)BATCH * SEQ * SEQ];

// ---------------------------------------------------------------------------
// PTX helpers — baseline (non arch-variant) instructions only:
// cp.async (sm_80), ldmatrix (sm_75), mma.sync bf16 (sm_80)
// ---------------------------------------------------------------------------
__device__ __forceinline__ uint32_t smem_u32(const void* p) {
    uint32_t a;
    asm("{ .reg .u64 t; cvta.to.shared.u64 t, %1; cvt.u32.u64 %0, t; }"
        : "=r"(a) : "l"(p));
    return a;
}
__device__ __forceinline__ uint32_t swz128(uint32_t o) { return o ^ ((o >> 3) & 0x70); }

__device__ __forceinline__ void cp16(uint32_t dst, const void* src) {
    asm volatile("cp.async.cg.shared.global [%0], [%1], 16;"
                 :: "r"(dst), "l"(__cvta_generic_to_global(src)) : "memory");
}
#define CP_COMMIT() asm volatile("cp.async.commit_group;" ::: "memory")
#define CP_WAIT1()  asm volatile("cp.async.wait_group 1;" ::: "memory")

__device__ __forceinline__ void ldsm_x4(uint32_t& r0, uint32_t& r1, uint32_t& r2,
                                        uint32_t& r3, uint32_t addr) {
    asm volatile("ldmatrix.sync.aligned.m8n8.x4.shared.b16 {%0,%1,%2,%3}, [%4];"
                 : "=r"(r0), "=r"(r1), "=r"(r2), "=r"(r3) : "r"(addr));
}
__device__ __forceinline__ void mma_bf16(float* d, const uint32_t* a, const uint32_t* b) {
    asm volatile(
        "mma.sync.aligned.m16n8k16.row.col.f32.bf16.bf16.f32 "
        "{%0,%1,%2,%3}, {%4,%5,%6,%7}, {%8,%9}, {%0,%1,%2,%3};"
        : "+f"(d[0]), "+f"(d[1]), "+f"(d[2]), "+f"(d[3])
        : "r"(a[0]), "r"(a[1]), "r"(a[2]), "r"(a[3]), "r"(b[0]), "r"(b[1]));
}

// ---------------------------------------------------------------------------
// Split-bf16 tensor-core GEMM:  C[M,N] = alpha * (A_hi+A_lo) @ (B_hi+B_lo)^T
//   A: [M,K] row-major (hi/lo bf16), B: [N,K] row-major (hi/lo bf16)
//   3 MMAs per k-step (hh + hl + lh), fp32 register accumulators.
//   CTA tile 128x128, K chunk 64 (128B SW128 rows), 2-stage cp.async pipe.
//   8 warps, 2x4 layout, warp tile 64x32 (4 m-frags x 4 n-frags).
//   EPI 0: fp32 out (alpha);  EPI 1: split hi/lo bf16 out.
// ---------------------------------------------------------------------------
#define KCHUNK       64
#define TILE_BYTES   16384              // 128 rows * 128B
#define STAGE_BYTES  (4 * TILE_BYTES)   // Ahi, Alo, Bhi, Blo
#define NSTAGES      2
#define GEMM_SMEM    (NSTAGES * STAGE_BYTES)   // 131072 B

template <int EPI>
__global__ void __launch_bounds__(256, 1)
gemm_mma(const __nv_bfloat16* __restrict__ Ah, const __nv_bfloat16* __restrict__ Al,
         const __nv_bfloat16* __restrict__ Bh, const __nv_bfloat16* __restrict__ Bl,
         float* __restrict__ Cf, __nv_bfloat16* __restrict__ Ch, __nv_bfloat16* __restrict__ Cl,
         int K, int lda, int ldb, int ldc, float alpha,
         long long sA, long long sB, long long sC)
{
    extern __shared__ __align__(1024) char smem[];
    const uint32_t sbase = smem_u32(smem);
    const int tid  = threadIdx.x;
    const int wid  = tid >> 5, lane = tid & 31;
    const int wm   = wid & 1;          // 0..1  (m dimension)
    const int wn   = wid >> 1;         // 0..3  (n dimension)

    Ah += blockIdx.z * sA;  Al += blockIdx.z * sA;
    Bh += blockIdx.z * sB;  Bl += blockIdx.z * sB;
    const int m0 = blockIdx.y * 128;
    const int n0 = blockIdx.x * 128;

    // ---- tile loader: 4096 x 16B cp.async per chunk (16 per thread) ----
    auto load_chunk = [&](int c) {
        const uint32_t stage = sbase + (c & (NSTAGES - 1)) * STAGE_BYTES;
        const int kb = c * KCHUNK;
        #pragma unroll
        for (int i = 0; i < 16; i++) {
            const int idx = tid + i * 256;
            const int t   = i >> 2;           // 0:Ahi 1:Alo 2:Bhi 3:Blo
            const int w   = idx & 1023;
            const int r   = w >> 3;           // row 0..127
            const int seg = w & 7;            // 16B segment
            const __nv_bfloat16* gp;
            if (t == 0)      gp = Ah + (long long)(m0 + r) * lda + kb + seg * 8;
            else if (t == 1) gp = Al + (long long)(m0 + r) * lda + kb + seg * 8;
            else if (t == 2) gp = Bh + (long long)(n0 + r) * ldb + kb + seg * 8;
            else             gp = Bl + (long long)(n0 + r) * ldb + kb + seg * 8;
            cp16(stage + t * TILE_BYTES + swz128(r * 128 + seg * 16), gp);
        }
        CP_COMMIT();
    };

    load_chunk(0);
    load_chunk(1);

    float acc[4][4][4];
    #pragma unroll
    for (int i = 0; i < 4; i++)
        #pragma unroll
        for (int j = 0; j < 4; j++)
            #pragma unroll
            for (int q = 0; q < 4; q++) acc[i][j][q] = 0.f;

    // per-lane ldmatrix row/chunk components
    const int lrow = lane & 15;          // row within 16-row group
    const int lkof = (lane >> 4) * 16;   // 16B chunk select (k halves)
    const int arow = wm * 64 + lrow;     // A row base for this lane
    const int brow = wn * 32 + lrow;     // B row base for this lane

    const int C = K / KCHUNK;
    for (int c = 0; c < C; c++) {
        CP_WAIT1();                      // chunk c resident
        __syncthreads();
        const uint32_t st = sbase + (c & (NSTAGES - 1)) * STAGE_BYTES;

        #pragma unroll
        for (int k16 = 0; k16 < 4; k16++) {
            const uint32_t kb = k16 * 32 + lkof;
            uint32_t ah[4][4], al[4][4], bh[4][2], bl[4][2];
            #pragma unroll
            for (int mf = 0; mf < 4; mf++) {
                const uint32_t ro = swz128((arow + mf * 16) * 128 + kb);
                ldsm_x4(ah[mf][0], ah[mf][1], ah[mf][2], ah[mf][3], st + ro);
                ldsm_x4(al[mf][0], al[mf][1], al[mf][2], al[mf][3], st + TILE_BYTES + ro);
            }
            #pragma unroll
            for (int p = 0; p < 2; p++) {   // covers n-frags 2p, 2p+1
                const uint32_t ro = swz128((brow + p * 16) * 128 + kb);
                uint32_t r0, r1, r2, r3;
                ldsm_x4(r0, r1, r2, r3, st + 2 * TILE_BYTES + ro);
                bh[2*p][0] = r0; bh[2*p][1] = r2; bh[2*p+1][0] = r1; bh[2*p+1][1] = r3;
                ldsm_x4(r0, r1, r2, r3, st + 3 * TILE_BYTES + ro);
                bl[2*p][0] = r0; bl[2*p][1] = r2; bl[2*p+1][0] = r1; bl[2*p+1][1] = r3;
            }
            #pragma unroll
            for (int mf = 0; mf < 4; mf++)
                #pragma unroll
                for (int nf = 0; nf < 4; nf++) {
                    mma_bf16(acc[mf][nf], ah[mf], bh[nf]);
                    mma_bf16(acc[mf][nf], ah[mf], bl[nf]);
                    mma_bf16(acc[mf][nf], al[mf], bh[nf]);
                }
        }
        __syncthreads();                 // all warps done reading stage c
        if (c + NSTAGES < C) load_chunk(c + NSTAGES);
        else CP_COMMIT();                // keep per-thread group count uniform
    }

    // ---- epilogue ----
    const int tq = lane >> 2;       // 0..7 (row within 8)
    const int tr = (lane & 3) * 2;  // col pair
    if (EPI == 0) {
        float* Cb = Cf + blockIdx.z * sC;
        #pragma unroll
        for (int mf = 0; mf < 4; mf++) {
            const int r = m0 + wm * 64 + mf * 16 + tq;
            #pragma unroll
            for (int nf = 0; nf < 4; nf++) {
                const int col = n0 + wn * 32 + nf * 8 + tr;
                float2 v0 = { acc[mf][nf][0] * alpha, acc[mf][nf][1] * alpha };
                float2 v1 = { acc[mf][nf][2] * alpha, acc[mf][nf][3] * alpha };
                *(float2*)&Cb[(long long)r * ldc + col]       = v0;
                *(float2*)&Cb[(long long)(r + 8) * ldc + col] = v1;
            }
        }
    } else {
        #pragma unroll
        for (int mf = 0; mf < 4; mf++) {
            const int r = m0 + wm * 64 + mf * 16 + tq;
            #pragma unroll
            for (int nf = 0; nf < 4; nf++) {
                const int col = n0 + wn * 32 + nf * 8 + tr;
                #pragma unroll
                for (int h = 0; h < 2; h++) {
                    const long long o = (long long)(r + 8 * h) * ldc + col;
                    float v0 = acc[mf][nf][2*h], v1 = acc[mf][nf][2*h+1];
                    __nv_bfloat16 h0 = __float2bfloat16(v0);
                    __nv_bfloat16 h1 = __float2bfloat16(v1);
                    __nv_bfloat16 l0 = __float2bfloat16(v0 - __bfloat162float(h0));
                    __nv_bfloat16 l1 = __float2bfloat16(v1 - __bfloat162float(h1));
                    __nv_bfloat162 hh = __halves2bfloat162(h0, h1);
                    __nv_bfloat162 ll = __halves2bfloat162(l0, l1);
                    *(uint32_t*)&Ch[o] = *(uint32_t*)&hh;
                    *(uint32_t*)&Cl[o] = *(uint32_t*)&ll;
                }
            }
        }
    }
}

// ---------------------------------------------------------------------------
// fp32 -> split bf16 (hi/lo)
// ---------------------------------------------------------------------------
__global__ void __launch_bounds__(256)
split_f32(const float* __restrict__ in, __nv_bfloat16* __restrict__ hi,
          __nv_bfloat16* __restrict__ lo, long long n4)
{
    long long i = (long long)blockIdx.x * blockDim.x + threadIdx.x;
    if (i >= n4) return;
    float4 v = ((const float4*)in)[i];
    __nv_bfloat16 h0 = __float2bfloat16(v.x), h1 = __float2bfloat16(v.y);
    __nv_bfloat16 h2 = __float2bfloat16(v.z), h3 = __float2bfloat16(v.w);
    __nv_bfloat162 a = __halves2bfloat162(h0, h1), b = __halves2bfloat162(h2, h3);
    uint2 uh = { *(uint32_t*)&a, *(uint32_t*)&b };
    __nv_bfloat16 l0 = __float2bfloat16(v.x - __bfloat162float(h0));
    __nv_bfloat16 l1 = __float2bfloat16(v.y - __bfloat162float(h1));
    __nv_bfloat16 l2 = __float2bfloat16(v.z - __bfloat162float(h2));
    __nv_bfloat16 l3 = __float2bfloat16(v.w - __bfloat162float(h3));
    __nv_bfloat162 c = __halves2bfloat162(l0, l1), d = __halves2bfloat162(l2, l3);
    uint2 ulv = { *(uint32_t*)&c, *(uint32_t*)&d };
    ((uint2*)hi)[i] = uh;
    ((uint2*)lo)[i] = ulv;
}

// ---------------------------------------------------------------------------
// V [b][s][d] fp32 -> Vt hi/lo [b][d][s] split bf16 (32x32 smem transpose)
// ---------------------------------------------------------------------------
__global__ void __launch_bounds__(256)
transpose_split(const float* __restrict__ V, __nv_bfloat16* __restrict__ Th,
                __nv_bfloat16* __restrict__ Tl)
{
    __shared__ float t[32][33];
    const int b = blockIdx.z;
    const int s0 = blockIdx.x * 32, d0 = blockIdx.y * 32;
    const int tx = threadIdx.x & 31, ty = threadIdx.x >> 5;  // 32x8
    const float* Vb = V + (long long)b * SEQ * DIM;
    #pragma unroll
    for (int j = 0; j < 4; j++)
        t[ty + 8*j][tx] = Vb[(long long)(s0 + ty + 8*j) * DIM + d0 + tx];
    __syncthreads();
    __nv_bfloat16* Thb = Th + (long long)b * DIM * SEQ;
    __nv_bfloat16* Tlb = Tl + (long long)b * DIM * SEQ;
    #pragma unroll
    for (int j = 0; j < 4; j++) {
        float v = t[tx][ty + 8*j];
        __nv_bfloat16 h = __float2bfloat16(v);
        __nv_bfloat16 l = __float2bfloat16(v - __bfloat162float(h));
        long long o = (long long)(d0 + ty + 8*j) * SEQ + s0 + tx;
        Thb[o] = h;  Tlb[o] = l;
    }
}

// ---------------------------------------------------------------------------
// Row softmax (4096 cols), IN-PLACE: reads fp32 row of g_SP, writes split
// bf16 P into the same 16KB row (Ph first 8KB, Pl second 8KB).
// All global reads complete before the first __syncthreads; writes happen
// after the last one -> no intra-block race. One block owns one row.
// ---------------------------------------------------------------------------
__device__ __forceinline__ float warpMax(float v) {
    #pragma unroll
    for (int o = 16; o; o >>= 1) v = fmaxf(v, __shfl_xor_sync(0xffffffffu, v, o));
    return v;
}
__device__ __forceinline__ float warpSum(float v) {
    #pragma unroll
    for (int o = 16; o; o >>= 1) v += __shfl_xor_sync(0xffffffffu, v, o);
    return v;
}

__global__ void __launch_bounds__(256)
softmax_inplace(float* __restrict__ SP)
{
    __shared__ float shm[8], shs[8];
    const size_t row = blockIdx.x;
    float* rowp = SP + row * (size_t)SEQ;
    const float4* r4 = (const float4*)rowp;
    const int tid = threadIdx.x, lane = tid & 31, wid = tid >> 5;

    float4 v[4];
    float m = -3.4e38f;
    #pragma unroll
    for (int i = 0; i < 4; i++) {
        v[i] = r4[tid + i * 256];
        m = fmaxf(m, fmaxf(fmaxf(v[i].x, v[i].y), fmaxf(v[i].z, v[i].w)));
    }
    m = warpMax(m);
    if (lane == 0) shm[wid] = m;
    __syncthreads();
    float bm = shm[0];
    #pragma unroll
    for (int i = 1; i < 8; i++) bm = fmaxf(bm, shm[i]);

    float s = 0.f;
    #pragma unroll
    for (int i = 0; i < 4; i++) {
        v[i].x = __expf(v[i].x - bm); v[i].y = __expf(v[i].y - bm);
        v[i].z = __expf(v[i].z - bm); v[i].w = __expf(v[i].w - bm);
        s += v[i].x + v[i].y + v[i].z + v[i].w;
    }
    s = warpSum(s);
    if (lane == 0) shs[wid] = s;
    __syncthreads();
    float bs = 0.f;
    #pragma unroll
    for (int i = 0; i < 8; i++) bs += shs[i];
    const float inv = 1.0f / bs;

    // Ph at byte offset 0 of the row, Pl at +SEQ bf16 elements (8KB)
    uint2* ph = (uint2*)rowp;
    uint2* pl = (uint2*)((__nv_bfloat16*)rowp + SEQ);
    #pragma unroll
    for (int i = 0; i < 4; i++) {
        float x0 = v[i].x * inv, x1 = v[i].y * inv, x2 = v[i].z * inv, x3 = v[i].w * inv;
        __nv_bfloat16 h0 = __float2bfloat16(x0), h1 = __float2bfloat16(x1);
        __nv_bfloat16 h2 = __float2bfloat16(x2), h3 = __float2bfloat16(x3);
        __nv_bfloat162 a = __halves2bfloat162(h0, h1), b = __halves2bfloat162(h2, h3);
        ph[tid + i * 256] = uint2{ *(uint32_t*)&a, *(uint32_t*)&b };
        __nv_bfloat16 l0 = __float2bfloat16(x0 - __bfloat162float(h0));
        __nv_bfloat16 l1 = __float2bfloat16(x1 - __bfloat162float(h1));
        __nv_bfloat16 l2 = __float2bfloat16(x2 - __bfloat162float(h2));
        __nv_bfloat16 l3 = __float2bfloat16(x3 - __bfloat162float(h3));
        __nv_bfloat162 c = __halves2bfloat162(l0, l1), d = __halves2bfloat162(l2, l3);
        pl[tid + i * 256] = uint2{ *(uint32_t*)&c, *(uint32_t*)&d };
    }
}

// ---------------------------------------------------------------------------
// Launch
// ---------------------------------------------------------------------------
extern "C" void kernel_launch(void* const* d_in, const int* in_sizes, int n_in,
                              void* d_out, int out_size)
{
    const float* x  = (const float*)d_in[0];
    const float* Wq = (const float*)d_in[1];
    const float* Wk = (const float*)d_in[2];
    const float* Wv = (const float*)d_in[3];
    float* out = (float*)d_out;

    __nv_bfloat16 *xh, *xl, *Wh, *Wl, *Qh, *Ql, *Kh, *Kl, *Vth, *Vtl;
    float *V, *SP;
    cudaGetSymbolAddress((void**)&xh, g_xh);   cudaGetSymbolAddress((void**)&xl, g_xl);
    cudaGetSymbolAddress((void**)&Wh, g_Wh);   cudaGetSymbolAddress((void**)&Wl, g_Wl);
    cudaGetSymbolAddress((void**)&Qh, g_Qh);   cudaGetSymbolAddress((void**)&Ql, g_Ql);
    cudaGetSymbolAddress((void**)&Kh, g_Kh);   cudaGetSymbolAddress((void**)&Kl, g_Kl);
    cudaGetSymbolAddress((void**)&V,  g_V);
    cudaGetSymbolAddress((void**)&Vth, g_Vth); cudaGetSymbolAddress((void**)&Vtl, g_Vtl);
    cudaGetSymbolAddress((void**)&SP, g_SP);

    cudaFuncSetAttribute(gemm_mma<0>, cudaFuncAttributeMaxDynamicSharedMemorySize, GEMM_SMEM);
    cudaFuncSetAttribute(gemm_mma<1>, cudaFuncAttributeMaxDynamicSharedMemorySize, GEMM_SMEM);

    const float scale = 1.0f / 32.0f;  // D^-0.5

    // 1) split inputs to hi/lo bf16
    split_f32<<<(MTOT * (long long)DIM / 4 + 255) / 256, 256>>>(x, xh, xl, (long long)MTOT * DIM / 4);
    const long long wn4 = (long long)DIM * DIM / 4;
    split_f32<<<(wn4 + 255) / 256, 256>>>(Wq, Wh + 0 * (size_t)DIM * DIM, Wl + 0 * (size_t)DIM * DIM, wn4);
    split_f32<<<(wn4 + 255) / 256, 256>>>(Wk, Wh + 1 * (size_t)DIM * DIM, Wl + 1 * (size_t)DIM * DIM, wn4);
    split_f32<<<(wn4 + 255) / 256, 256>>>(Wv, Wh + 2 * (size_t)DIM * DIM, Wl + 2 * (size_t)DIM * DIM, wn4);

    // 2) projections: [16384,1024] = x @ W^T
    {
        dim3 grid(DIM / 128, MTOT / 128, 1);
        gemm_mma<1><<<grid, 256, GEMM_SMEM>>>(xh, xl, Wh + 0 * (size_t)DIM * DIM, Wl + 0 * (size_t)DIM * DIM,
                                              nullptr, Qh, Ql, DIM, DIM, DIM, DIM, 1.f, 0, 0, 0);
        gemm_mma<1><<<grid, 256, GEMM_SMEM>>>(xh, xl, Wh + 1 * (size_t)DIM * DIM, Wl + 1 * (size_t)DIM * DIM,
                                              nullptr, Kh, Kl, DIM, DIM, DIM, DIM, 1.f, 0, 0, 0);
        gemm_mma<0><<<grid, 256, GEMM_SMEM>>>(xh, xl, Wh + 2 * (size_t)DIM * DIM, Wl + 2 * (size_t)DIM * DIM,
                                              V, nullptr, nullptr, DIM, DIM, DIM, DIM, 1.f, 0, 0, 0);
    }

    // 3) V -> Vt split (bf16 [b][d][s])
    transpose_split<<<dim3(SEQ / 32, DIM / 32, BATCH), 256>>>(V, Vth, Vtl);

    // 4) scores: SP[b] = scale * Q[b] @ K[b]^T   (fp32)
    gemm_mma<0><<<dim3(SEQ / 128, SEQ / 128, BATCH), 256, GEMM_SMEM>>>(
        Qh, Ql, Kh, Kl, SP, nullptr, nullptr,
        DIM, DIM, DIM, SEQ, scale,
        (long long)SEQ * DIM, (long long)SEQ * DIM, (long long)SEQ * SEQ);

    // 5) softmax in-place -> split bf16 P (row stride 2*SEQ bf16)
    softmax_inplace<<<BATCH * SEQ, 256>>>(SP);

    // 6) out[b] = P[b] @ Vt[b]^T   (Ph rows at stride 2*SEQ, Pl = Ph + SEQ)
    {
        const __nv_bfloat16* Phb = (const __nv_bfloat16*)SP;
        const __nv_bfloat16* Plb = Phb + SEQ;
        gemm_mma<0><<<dim3(DIM / 128, SEQ / 128, BATCH), 256, GEMM_SMEM>>>(
            Phb, Plb, Vth, Vtl, out, nullptr, nullptr,
            SEQ, 2 * SEQ, SEQ, DIM, 1.f,
            (long long)SEQ * 2 * SEQ, (long long)DIM * SEQ, (long long)SEQ * DIM);
    }
}